// round 10
// baseline (speedup 1.0000x reference)
#include <cuda_runtime.h>
#include <cuda_bf16.h>
#include <math.h>

// Problem shape (fixed by the reference):
//   q,k,v: [H, N, D] fp32   adj: [H, N, N] fp32   alpha,beta: [H] fp32
//   out:   [H, N, D] fp32
#define HH 8
#define NN 4096
#define DD 64

// ---------------------------------------------------------------------------
// Math identity:
//   P = softmax(Q K^T * scale + adj)
//   out[h,n,:] = beta[h]*(P[h,n,:] @ V[h]) + (alpha[h] - beta[h]*P[h,n,n])*v[h,n,:]
//
// Kernel 1 (copy, 2048x256, no smem): out = alpha*v for every element of heads
//   with beta==0 (exact full answer for those heads). Loads are issued
//   unconditionally so nothing waits on the beta value; only the store is
//   predicated. Streaming stores keep v L2-resident across graph replays.
// Kernel 2 (correction, 8 CTAs = 1/head): only if beta[h] != 0, writes the
//   COMPLETE value b*(P@V) + (a - b*P_rr)*v_r for all rows of head h.
//   For beta[h]==0 it exits after one load -> ~pure launch overhead.
// Writes are disjoint (partitioned by beta[h]) -> no inter-kernel ordering
// requirement, deterministic output.
// ---------------------------------------------------------------------------

__device__ __forceinline__ void st_stream_f4(float4* p, float4 val) {
    asm volatile("st.global.cs.v4.f32 [%0], {%1,%2,%3,%4};"
                 :: "l"(p), "f"(val.x), "f"(val.y), "f"(val.z), "f"(val.w)
                 : "memory");
}

// ---- kernel 1: predicated scale-copy, one float4 per thread ----
__global__ void __launch_bounds__(256)
alpha_v_copy_kernel(const float* __restrict__ v,
                    const float* __restrict__ alpha,
                    const float* __restrict__ beta,
                    float* __restrict__ out) {
    const int i = blockIdx.x * 256 + threadIdx.x;   // float4 index, exact cover
    const int h = i >> 16;                          // i / (N*D/4) = i / 65536
    float4 t = ((const float4*)v)[i];               // issue immediately
    const float a = __ldg(&alpha[h]);
    const float b = __ldg(&beta[h]);
    if (b == 0.0f) {
        t.x *= a; t.y *= a; t.z *= a; t.w *= a;
        st_stream_f4(((float4*)out) + i, t);
    }
}

// ---- kernel 2: per-head full-softmax correction (general path) ----
#define CTHREADS 1024
__global__ void __launch_bounds__(CTHREADS)
attn_correction_kernel(const float* __restrict__ q,
                       const float* __restrict__ k,
                       const float* __restrict__ v,
                       const float* __restrict__ adj,
                       const float* __restrict__ alpha,
                       const float* __restrict__ beta,
                       float* __restrict__ out) {
    const int h = blockIdx.x;
    const float b = __ldg(&beta[h]);
    if (b == 0.0f) return;    // exact: correction is identically zero

    __shared__ float s[NN];            // 16 KB: scores -> exp weights, one row
    __shared__ float qs[DD];
    __shared__ float red[CTHREADS];    // 4 KB

    const int tid = threadIdx.x;
    const float a     = __ldg(&alpha[h]);
    const float scale = rsqrtf((float)DD);
    const float* kh = k + (long)h * NN * DD;
    const float* vh = v + (long)h * NN * DD;

    for (int r = 0; r < NN; r++) {
        if (tid < DD) qs[tid] = q[((long)h * NN + r) * DD + tid];
        __syncthreads();

        const float* adjr = adj + ((long)h * NN + r) * NN;

        // scores + running max
        float lmax = -INFINITY;
        for (int m = tid; m < NN; m += CTHREADS) {
            const float* km = kh + (long)m * DD;
            float dot = 0.f;
            #pragma unroll 16
            for (int d = 0; d < DD; d++) dot = fmaf(qs[d], km[d], dot);
            float val = dot * scale + adjr[m];
            s[m] = val;
            lmax = fmaxf(lmax, val);
        }
        red[tid] = lmax; __syncthreads();
        for (int o = CTHREADS / 2; o > 0; o >>= 1) {
            if (tid < o) red[tid] = fmaxf(red[tid], red[tid + o]);
            __syncthreads();
        }
        const float mx = red[0]; __syncthreads();

        // exp + sum
        float lsum = 0.f;
        for (int m = tid; m < NN; m += CTHREADS) {
            float e = expf(s[m] - mx);
            s[m] = e;
            lsum += e;
        }
        red[tid] = lsum; __syncthreads();
        for (int o = CTHREADS / 2; o > 0; o >>= 1) {
            if (tid < o) red[tid] += red[tid + o];
            __syncthreads();
        }
        const float inv = 1.0f / red[0]; __syncthreads();
        const float prr = s[r] * inv;    // P[r,r]

        // weighted V accumulate: thread t -> dim d = t&63, group g = t>>6 (16)
        const int d = tid & 63, g = tid >> 6;
        float acc = 0.f;
        for (int m = g; m < NN; m += 16) acc += s[m] * vh[(long)m * DD + d];
        red[tid] = acc; __syncthreads();
        if (g == 0) {
            float tot = 0.f;
            #pragma unroll
            for (int j = 0; j < 16; j++) tot += red[d + 64 * j];
            // complete value: b*(P@V) + (a - b*P_rr)*v_r
            out[((long)h * NN + r) * DD + d] =
                b * tot * inv + (a - b * prr) * vh[(long)r * DD + d];
        }
        __syncthreads();
    }
}

extern "C" void kernel_launch(void* const* d_in, const int* in_sizes, int n_in,
                              void* d_out, int out_size) {
    const float* q     = (const float*)d_in[0];
    const float* k     = (const float*)d_in[1];
    const float* v     = (const float*)d_in[2];
    const float* adj   = (const float*)d_in[3];
    const float* alpha = (const float*)d_in[4];
    const float* beta  = (const float*)d_in[5];
    float* out = (float*)d_out;

    // 2048 blocks x 256 threads: one float4 per thread covers H*N*D/4 exactly.
    alpha_v_copy_kernel<<<(HH * NN * DD / 4) / 256, 256>>>(v, alpha, beta, out);

    // One CTA per head; early-exits unless beta[h] != 0.
    attn_correction_kernel<<<HH, CTHREADS>>>(q, k, v, adj, alpha, beta, out);
}